// round 1
// baseline (speedup 1.0000x reference)
#include <cuda_runtime.h>
#include <math.h>

#define BATCH 512
#define CIN_  5
#define LEN   1024
#define COUT_ 32
#define NA    13
#define NBND  5

// scratch (no allocation allowed): per-block stat partials + finalized BN affine + T sums
__device__ float g_partial[BATCH * 40];
__device__ float g_scale[64];
__device__ float g_shift[64];
__device__ float g_T[10];

// ---------------------------------------------------------------------------
// K1: per-batch partial sums of depthwise outputs: D1[5], G1[15], D2[5], G2[15]
// (BN mean/var of y = pw * dc follow exactly from these via linearity)
// ---------------------------------------------------------------------------
__global__ __launch_bounds__(256) void k_stats(const float* __restrict__ src,
                                               const float* __restrict__ dw1,
                                               const float* __restrict__ dw2) {
    __shared__ float s_src[5 * 1032];   // [c][p], p = l+2 (halo of 2 each side, zero padded)
    __shared__ float s_red[8 * 40];
    int b = blockIdx.x, tid = threadIdx.x;

    float w1[5][5], w2[5][3];
#pragma unroll
    for (int c = 0; c < 5; c++) {
#pragma unroll
        for (int k = 0; k < 5; k++) w1[c][k] = __ldg(&dw1[c * 5 + k]);
#pragma unroll
        for (int k = 0; k < 3; k++) w2[c][k] = __ldg(&dw2[c * 3 + k]);
    }

    for (int idx = tid; idx < 5 * 1032; idx += 256) {
        int c = idx / 1032, p = idx - c * 1032;
        float v = 0.f;
        if (p >= 2 && p < 1026) v = src[(b * 5 + c) * 1024 + (p - 2)];
        s_src[idx] = v;
    }
    __syncthreads();

    // v[0..4]=D1, v[5..19]=G1, v[20..24]=D2, v[25..39]=G2
    float v[40];
#pragma unroll
    for (int j = 0; j < 40; j++) v[j] = 0.f;

#pragma unroll
    for (int i = 0; i < 4; i++) {
        int l = tid + i * 256;
        float d1[5], d2[5];
#pragma unroll
        for (int c = 0; c < 5; c++) {
            const float* sp = &s_src[c * 1032 + l];
            float a1 = 0.f;
#pragma unroll
            for (int k = 0; k < 5; k++) a1 = fmaf(w1[c][k], sp[k], a1);
            float a2 = 0.f;
#pragma unroll
            for (int k = 0; k < 3; k++) a2 = fmaf(w2[c][k], sp[k + 1], a2);
            d1[c] = a1; d2[c] = a2;
            v[c] += a1; v[20 + c] += a2;
        }
        int gi = 0;
#pragma unroll
        for (int c = 0; c < 5; c++)
#pragma unroll
            for (int c2 = c; c2 < 5; c2++, gi++) {
                v[5 + gi]  = fmaf(d1[c], d1[c2], v[5 + gi]);
                v[25 + gi] = fmaf(d2[c], d2[c2], v[25 + gi]);
            }
    }

#pragma unroll
    for (int j = 0; j < 40; j++) {
#pragma unroll
        for (int off = 16; off > 0; off >>= 1)
            v[j] += __shfl_xor_sync(0xffffffffu, v[j], off);
    }
    int w = tid >> 5, lid = tid & 31;
    if (lid == 0) {
#pragma unroll
        for (int j = 0; j < 40; j++) s_red[w * 40 + j] = v[j];
    }
    __syncthreads();
    if (tid < 40) {
        float s = 0.f;
#pragma unroll
        for (int k = 0; k < 8; k++) s += s_red[k * 40 + tid];
        g_partial[b * 40 + tid] = s;   // fully written each call: deterministic
    }
}

// ---------------------------------------------------------------------------
// K2: reduce partials -> BN affine coefs (scale/shift per 64 channels); T[10]
// ---------------------------------------------------------------------------
__global__ __launch_bounds__(256) void k_finalize(
    const float* __restrict__ pw1, const float* __restrict__ g1, const float* __restrict__ be1,
    const float* __restrict__ pw2, const float* __restrict__ g2, const float* __restrict__ be2,
    const float* __restrict__ flw) {
    __shared__ float s_part[6 * 40];
    __shared__ float stats[40];
    int tid = threadIdx.x;

    if (tid < 240) {
        int j = tid % 40, slice = tid / 40;
        float s = 0.f;
        for (int b = slice; b < BATCH; b += 6) s += g_partial[b * 40 + j];
        s_part[slice * 40 + j] = s;
    }

    // T[nn] = sum_l flw[nn%5][ (nn/5)*1024 + l ]
    int w = tid >> 5, lid = tid & 31;
    for (int nn = w; nn < 10; nn += 8) {
        int n = nn % 5, half = nn / 5;
        float s = 0.f;
        for (int l = lid; l < 1024; l += 32) s += __ldg(&flw[n * 2048 + half * 1024 + l]);
#pragma unroll
        for (int off = 16; off > 0; off >>= 1) s += __shfl_xor_sync(0xffffffffu, s, off);
        if (lid == 0) g_T[nn] = s;
    }
    __syncthreads();
    if (tid < 40) {
        float s = 0.f;
#pragma unroll
        for (int k = 0; k < 6; k++) s += s_part[k * 40 + tid];
        stats[tid] = s;
    }
    __syncthreads();

    if (tid < 64) {
        int o = tid;
        bool br1 = (o < 32);
        int oc = br1 ? o : o - 32;
        const float* pw = br1 ? pw1 : pw2;
        int db = br1 ? 0 : 20;
        float pc[5];
        float m = 0.f;
#pragma unroll
        for (int c = 0; c < 5; c++) {
            pc[c] = pw[oc * 5 + c];
            m = fmaf(pc[c], stats[db + c], m);
        }
        const float invN = 1.f / (float)(BATCH * LEN);
        m *= invN;
        float e2 = 0.f;
        int gi = 0;
#pragma unroll
        for (int c = 0; c < 5; c++)
#pragma unroll
            for (int c2 = c; c2 < 5; c2++, gi++) {
                float mult = (c == c2) ? 1.f : 2.f;
                e2 = fmaf(mult * pc[c] * pc[c2], stats[db + 5 + gi], e2);
            }
        e2 *= invN;
        float var = e2 - m * m;
        float gg = br1 ? g1[oc] : g2[oc];
        float bb = br1 ? be1[oc] : be2[oc];
        float sc = gg * rsqrtf(var + 1e-5f);
        g_scale[o] = sc;
        g_shift[o] = bb - m * sc;
    }
}

// ---------------------------------------------------------------------------
// K3: fused main kernel, one block per batch element.
//   stage 1: src + F -> smem;  stage 2: depthwise dc -> smem
//   stage 3: per-warp channels: x = relu(bn(pw·dc))·(rw·src+rb), S[c,n]=Σ x·F[n,l]
//   stage 4: PQ[a,n] = ll1w·S + ll1b·T;  stage 5: out[i,j,n]=PQ[mn,n]+PQ[mx,5+n]+flb
// ---------------------------------------------------------------------------
#define SMEM_FLOATS (5 * 1032 + 10 * 1024 + 10 * 1024 + 640 + 130)
#define SMEM_BYTES  (SMEM_FLOATS * 4)

__global__ __launch_bounds__(256) void k_main(
    const float* __restrict__ src,
    const float* __restrict__ dw1, const float* __restrict__ dw2,
    const float* __restrict__ pw1, const float* __restrict__ pw2,
    const float* __restrict__ r1w, const float* __restrict__ r1b,
    const float* __restrict__ r2w, const float* __restrict__ r2b,
    const float* __restrict__ ll1w, const float* __restrict__ ll1b,
    const float* __restrict__ flw, const float* __restrict__ flb,
    float* __restrict__ out) {
    extern __shared__ float sm[];
    float* s_src = sm;                       // 5*1032
    float* s_dc  = s_src + 5 * 1032;         // 10*1024 (rows 0..4 dc1, 5..9 dc2)
    float* s_F   = s_dc + 10 * 1024;         // 10*1024
    float* s_S   = s_F + 10 * 1024;          // 64*10
    float* s_PQ  = s_S + 640;                // 13*10

    int b = blockIdx.x, tid = threadIdx.x;

    for (int idx = tid; idx < 5 * 1032; idx += 256) {
        int c = idx / 1032, p = idx - c * 1032;
        float v = 0.f;
        if (p >= 2 && p < 1026) v = src[(b * 5 + c) * 1024 + (p - 2)];
        s_src[idx] = v;
    }
    for (int idx = tid; idx < 10 * 1024; idx += 256) {
        int nn = idx >> 10, l = idx & 1023;
        s_F[idx] = __ldg(&flw[(nn % 5) * 2048 + (nn / 5) * 1024 + l]);
    }
    __syncthreads();

    for (int idx = tid; idx < 10 * 1024; idx += 256) {
        int row = idx >> 10, l = idx & 1023;
        float a = 0.f;
        if (row < 5) {
            const float* sp = &s_src[row * 1032 + l];
#pragma unroll
            for (int k = 0; k < 5; k++) a = fmaf(__ldg(&dw1[row * 5 + k]), sp[k], a);
        } else {
            int c = row - 5;
            const float* sp = &s_src[c * 1032 + l];
#pragma unroll
            for (int k = 0; k < 3; k++) a = fmaf(__ldg(&dw2[c * 3 + k]), sp[k + 1], a);
        }
        s_dc[idx] = a;
    }
    __syncthreads();

    int w = tid >> 5, lid = tid & 31;
    // warp w owns channels [w*8, w*8+8); 4 passes of 2 channels
#pragma unroll 1
    for (int pass = 0; pass < 4; pass++) {
        int o0 = w * 8 + pass * 2;
        bool br1 = (o0 < 32);
        const float* pw = br1 ? pw1 : pw2;
        const float* rw = br1 ? r1w : r2w;
        const float* rb_ = br1 ? r1b : r2b;
        const float* dcb = s_dc + (br1 ? 0 : 5 * 1024);

        float pwc[2][5], rwc[2][5], sc[2], sh[2], rb[2];
#pragma unroll
        for (int u = 0; u < 2; u++) {
            int o = o0 + u;
            int oc = br1 ? o : o - 32;
#pragma unroll
            for (int c = 0; c < 5; c++) {
                pwc[u][c] = __ldg(&pw[oc * 5 + c]);
                rwc[u][c] = __ldg(&rw[oc * 5 + c]);
            }
            rb[u] = __ldg(&rb_[oc]);
            sc[u] = g_scale[o];
            sh[u] = g_shift[o];
        }

        float acc[2][10];
#pragma unroll
        for (int u = 0; u < 2; u++)
#pragma unroll
            for (int n = 0; n < 10; n++) acc[u][n] = 0.f;

#pragma unroll 4
        for (int it = 0; it < 32; it++) {
            int l = lid + it * 32;
            float xv[2];
#pragma unroll
            for (int u = 0; u < 2; u++) {
                float y = 0.f, z = rb[u];
#pragma unroll
                for (int c = 0; c < 5; c++) {
                    y = fmaf(pwc[u][c], dcb[c * 1024 + l], y);
                    z = fmaf(rwc[u][c], s_src[c * 1032 + l + 2], z);
                }
                float t = fmaf(y, sc[u], sh[u]);
                xv[u] = fmaxf(t, 0.f) * z;
            }
#pragma unroll
            for (int n = 0; n < 10; n++) {
                float f = s_F[n * 1024 + l];
                acc[0][n] = fmaf(xv[0], f, acc[0][n]);
                acc[1][n] = fmaf(xv[1], f, acc[1][n]);
            }
        }

#pragma unroll
        for (int u = 0; u < 2; u++)
#pragma unroll
            for (int n = 0; n < 10; n++) {
#pragma unroll
                for (int off = 16; off > 0; off >>= 1)
                    acc[u][n] += __shfl_xor_sync(0xffffffffu, acc[u][n], off);
            }
        if (lid < 10) {
            s_S[o0 * 10 + lid]       = acc[0][lid];
            s_S[(o0 + 1) * 10 + lid] = acc[1][lid];
        }
    }
    __syncthreads();

    // PQ[a][n] = sum_c ll1w[a,c]*S[c,n] + ll1b[a]*T[n]
    if (tid < 130) {
        int a = tid / 10, n = tid - a * 10;
        float p = __ldg(&ll1b[a]) * g_T[n];
#pragma unroll 8
        for (int c = 0; c < 64; c++) p = fmaf(__ldg(&ll1w[a * 64 + c]), s_S[c * 10 + n], p);
        s_PQ[tid] = p;
    }
    __syncthreads();

    float* outp = out + b * (NA * NA * NBND);
    for (int t = tid; t < NA * NA * NBND; t += 256) {
        int i = t / (NA * NBND);
        int r = t - i * (NA * NBND);
        int j = r / NBND;
        int n = r - j * NBND;
        int mn = min(i, j), mx = max(i, j);
        outp[t] = s_PQ[mn * 10 + n] + s_PQ[mx * 10 + 5 + n] + __ldg(&flb[n]);
    }
}

// ---------------------------------------------------------------------------
extern "C" void kernel_launch(void* const* d_in, const int* in_sizes, int n_in,
                              void* d_out, int out_size) {
    const float* src  = (const float*)d_in[0];
    // d_in[1] = mask (unused), d_in[2] = max_atoms (compile-time 13)
    const float* dw1  = (const float*)d_in[3];
    const float* pw1  = (const float*)d_in[4];
    const float* g1   = (const float*)d_in[5];
    const float* be1  = (const float*)d_in[6];
    const float* r1w  = (const float*)d_in[7];
    const float* r1b  = (const float*)d_in[8];
    const float* dw2  = (const float*)d_in[9];
    const float* pw2  = (const float*)d_in[10];
    const float* g2   = (const float*)d_in[11];
    const float* be2  = (const float*)d_in[12];
    const float* r2w  = (const float*)d_in[13];
    const float* r2b  = (const float*)d_in[14];
    const float* ll1w = (const float*)d_in[15];
    const float* ll1b = (const float*)d_in[16];
    const float* flw  = (const float*)d_in[17];
    const float* flb  = (const float*)d_in[18];
    float* out = (float*)d_out;

    cudaFuncSetAttribute(k_main, cudaFuncAttributeMaxDynamicSharedMemorySize, SMEM_BYTES);

    k_stats<<<BATCH, 256>>>(src, dw1, dw2);
    k_finalize<<<1, 256>>>(pw1, g1, be1, pw2, g2, be2, flw);
    k_main<<<BATCH, 256, SMEM_BYTES>>>(src, dw1, dw2, pw1, pw2, r1w, r1b, r2w, r2b,
                                       ll1w, ll1b, flw, flb, out);
}

// round 2
// speedup vs baseline: 1.1132x; 1.1132x over previous
#include <cuda_runtime.h>
#include <math.h>

#define BATCH 512
#define LEN   1024
#define NA    13
#define NBND  5

typedef unsigned long long ull;

__device__ float g_partial[BATCH * 40];
__device__ float g_scale[64];
__device__ float g_shift[64];
__device__ float g_T[10];

// ---- f32x2 helpers (FFMA2 only reachable via PTX) ----
__device__ __forceinline__ ull pack2(float lo, float hi) {
    ull r; asm("mov.b64 %0, {%1, %2};" : "=l"(r) : "f"(lo), "f"(hi)); return r;
}
__device__ __forceinline__ void unpack2(ull v, float& lo, float& hi) {
    asm("mov.b64 {%0, %1}, %2;" : "=f"(lo), "=f"(hi) : "l"(v));
}
__device__ __forceinline__ ull fma2(ull a, ull b, ull c) {
    ull d; asm("fma.rn.f32x2 %0, %1, %2, %3;" : "=l"(d) : "l"(a), "l"(b), "l"(c)); return d;
}

// ---------------------------------------------------------------------------
// K1: per-batch partials D1[5],G1[15],D2[5],G2[15] — direct global loads,
// register sliding windows, one shuffle reduction. No smem staging.
// ---------------------------------------------------------------------------
__global__ __launch_bounds__(256) void k_stats(const float* __restrict__ src,
                                               const float* __restrict__ dw1,
                                               const float* __restrict__ dw2) {
    __shared__ float s_red[8 * 40];
    int b = blockIdx.x, tid = threadIdx.x;
    int l0 = tid * 4;                       // 4 outputs per thread
    const float* sb = src + b * 5 * 1024;

    float w1[5][5], w2[5][3];
#pragma unroll
    for (int c = 0; c < 5; c++) {
#pragma unroll
        for (int k = 0; k < 5; k++) w1[c][k] = __ldg(&dw1[c * 5 + k]);
#pragma unroll
        for (int k = 0; k < 3; k++) w2[c][k] = __ldg(&dw2[c * 3 + k]);
    }

    // windows x[c][0..7] = src[c][l0-2 .. l0+5] (zero padded at edges)
    float x[5][8];
#pragma unroll
    for (int c = 0; c < 5; c++) {
        const float* p = sb + c * 1024 + l0;
        float4 m = *(const float4*)p;
        x[c][2] = m.x; x[c][3] = m.y; x[c][4] = m.z; x[c][5] = m.w;
        if (l0 >= 2) { float2 e = *(const float2*)(p - 2); x[c][0] = e.x; x[c][1] = e.y; }
        else         { x[c][0] = 0.f; x[c][1] = 0.f; }
        if (l0 + 5 < 1024) { float2 e = *(const float2*)(p + 4); x[c][6] = e.x; x[c][7] = e.y; }
        else               { x[c][6] = 0.f; x[c][7] = 0.f; }
    }

    float v[40];
#pragma unroll
    for (int j = 0; j < 40; j++) v[j] = 0.f;

#pragma unroll
    for (int j = 0; j < 4; j++) {           // 4 output positions
        float d1[5], d2[5];
#pragma unroll
        for (int c = 0; c < 5; c++) {
            float a1 = 0.f;
#pragma unroll
            for (int k = 0; k < 5; k++) a1 = fmaf(w1[c][k], x[c][j + k], a1);
            float a2 = 0.f;
#pragma unroll
            for (int k = 0; k < 3; k++) a2 = fmaf(w2[c][k], x[c][j + k + 1], a2);
            d1[c] = a1; d2[c] = a2;
            v[c] += a1; v[20 + c] += a2;
        }
        int gi = 0;
#pragma unroll
        for (int c = 0; c < 5; c++)
#pragma unroll
            for (int c2 = c; c2 < 5; c2++, gi++) {
                v[5 + gi]  = fmaf(d1[c], d1[c2], v[5 + gi]);
                v[25 + gi] = fmaf(d2[c], d2[c2], v[25 + gi]);
            }
    }

#pragma unroll
    for (int j = 0; j < 40; j++) {
#pragma unroll
        for (int off = 16; off > 0; off >>= 1)
            v[j] += __shfl_xor_sync(0xffffffffu, v[j], off);
    }
    int w = tid >> 5, lid = tid & 31;
    if (lid == 0) {
#pragma unroll
        for (int j = 0; j < 40; j++) s_red[w * 40 + j] = v[j];
    }
    __syncthreads();
    if (tid < 40) {
        float s = 0.f;
#pragma unroll
        for (int k = 0; k < 8; k++) s += s_red[k * 40 + tid];
        g_partial[b * 40 + tid] = s;
    }
}

// ---------------------------------------------------------------------------
// K2: reduce partials -> BN affine (scale/shift per 64 ch); T[10]
// ---------------------------------------------------------------------------
__global__ __launch_bounds__(256) void k_finalize(
    const float* __restrict__ pw1, const float* __restrict__ g1, const float* __restrict__ be1,
    const float* __restrict__ pw2, const float* __restrict__ g2, const float* __restrict__ be2,
    const float* __restrict__ flw) {
    __shared__ float s_part[6 * 40];
    __shared__ float stats[40];
    int tid = threadIdx.x;

    if (tid < 240) {
        int j = tid % 40, slice = tid / 40;
        float s = 0.f;
        for (int b = slice; b < BATCH; b += 6) s += g_partial[b * 40 + j];
        s_part[slice * 40 + j] = s;
    }

    int w = tid >> 5, lid = tid & 31;
    for (int nn = w; nn < 10; nn += 8) {
        int n = nn % 5, half = nn / 5;
        float s = 0.f;
        for (int l = lid; l < 1024; l += 32) s += __ldg(&flw[n * 2048 + half * 1024 + l]);
#pragma unroll
        for (int off = 16; off > 0; off >>= 1) s += __shfl_xor_sync(0xffffffffu, s, off);
        if (lid == 0) g_T[nn] = s;
    }
    __syncthreads();
    if (tid < 40) {
        float s = 0.f;
#pragma unroll
        for (int k = 0; k < 6; k++) s += s_part[k * 40 + tid];
        stats[tid] = s;
    }
    __syncthreads();

    if (tid < 64) {
        int o = tid;
        bool br1 = (o < 32);
        int oc = br1 ? o : o - 32;
        const float* pw = br1 ? pw1 : pw2;
        int db = br1 ? 0 : 20;
        float pc[5];
        float m = 0.f;
#pragma unroll
        for (int c = 0; c < 5; c++) {
            pc[c] = pw[oc * 5 + c];
            m = fmaf(pc[c], stats[db + c], m);
        }
        const float invN = 1.f / (float)(BATCH * LEN);
        m *= invN;
        float e2 = 0.f;
        int gi = 0;
#pragma unroll
        for (int c = 0; c < 5; c++)
#pragma unroll
            for (int c2 = c; c2 < 5; c2++, gi++) {
                float mult = (c == c2) ? 1.f : 2.f;
                e2 = fmaf(mult * pc[c] * pc[c2], stats[db + 5 + gi], e2);
            }
        e2 *= invN;
        float var = e2 - m * m;
        float gg = br1 ? g1[oc] : g2[oc];
        float bb = br1 ? be1[oc] : be2[oc];
        float sc = gg * rsqrtf(var + 1e-5f);
        g_scale[o] = sc;
        g_shift[o] = bb - m * sc;
    }
}

// ---------------------------------------------------------------------------
// K3: fused main kernel. 512 threads, 16 warps, 1 block per batch.
// Interleaved (dc,src) pairs + F n-pairs in smem; FFMA2 everywhere.
// ---------------------------------------------------------------------------
#define SM_SRC 0                         // 5*1032 floats
#define SM_D1  (5 * 1032)                // 5*1024 float2 (dc1, src)
#define SM_D2  (SM_D1 + 10240)           // 5*1024 float2 (dc2, src)
#define SM_F2  (SM_D2 + 10240)           // 5*1024 float2 (F[2p], F[2p+1])
#define SM_L   (SM_F2 + 10240)           // 13*64  ll1w
#define SM_S   (SM_L + 832)              // 64*10
#define SM_PQ  (SM_S + 640)              // 13*10
#define SMEM_FLOATS (SM_PQ + 130)
#define SMEM_BYTES  (SMEM_FLOATS * 4)

__global__ __launch_bounds__(512, 1) void k_main(
    const float* __restrict__ src,
    const float* __restrict__ dw1, const float* __restrict__ dw2,
    const float* __restrict__ pw1, const float* __restrict__ pw2,
    const float* __restrict__ r1w, const float* __restrict__ r1b,
    const float* __restrict__ r2w, const float* __restrict__ r2b,
    const float* __restrict__ ll1w, const float* __restrict__ ll1b,
    const float* __restrict__ flw, const float* __restrict__ flb,
    float* __restrict__ out) {
    extern __shared__ float sm[];
    int b = blockIdx.x, tid = threadIdx.x;
    int w = tid >> 5, lid = tid & 31;

    // ---- stage 1: load src (halo), build F2 pairs, load ll1w ----
    for (int idx = tid; idx < 5 * 1032; idx += 512) {
        int c = idx / 1032, p = idx - c * 1032;
        float v = 0.f;
        if (p >= 2 && p < 1026) v = src[(b * 5 + c) * 1024 + (p - 2)];
        sm[SM_SRC + idx] = v;
    }
    {
        ull* f2 = (ull*)(sm + SM_F2);
        for (int idx = tid; idx < 5 * 1024; idx += 512) {
            int p = idx >> 10, l = idx & 1023;
            int n0 = 2 * p, n1 = 2 * p + 1;
            float v0 = __ldg(&flw[(n0 % 5) * 2048 + (n0 / 5) * 1024 + l]);
            float v1 = __ldg(&flw[(n1 % 5) * 2048 + (n1 / 5) * 1024 + l]);
            f2[idx] = pack2(v0, v1);
        }
    }
    for (int idx = tid; idx < NA * 64; idx += 512) sm[SM_L + idx] = __ldg(&ll1w[idx]);
    __syncthreads();

    // ---- stage 2: depthwise convs, interleave with src ----
    {
        ull* d1 = (ull*)(sm + SM_D1);
        ull* d2 = (ull*)(sm + SM_D2);
        float wa[5][5], wb[5][3];
#pragma unroll
        for (int c = 0; c < 5; c++) {
#pragma unroll
            for (int k = 0; k < 5; k++) wa[c][k] = __ldg(&dw1[c * 5 + k]);
#pragma unroll
            for (int k = 0; k < 3; k++) wb[c][k] = __ldg(&dw2[c * 3 + k]);
        }
#pragma unroll
        for (int i = 0; i < 10; i++) {
            int idx = tid + i * 512;
            int c = idx >> 10, l = idx & 1023;
            const float* sp = &sm[SM_SRC + c * 1032 + l];
            float a1 = 0.f;
#pragma unroll
            for (int k = 0; k < 5; k++) a1 = fmaf(wa[c][k], sp[k], a1);
            float a2 = 0.f;
#pragma unroll
            for (int k = 0; k < 3; k++) a2 = fmaf(wb[c][k], sp[k + 1], a2);
            float sv = sp[2];
            d1[idx] = pack2(a1, sv);
            d2[idx] = pack2(a2, sv);
        }
    }
    __syncthreads();

    // ---- stage 3: each warp: 4 channels, full L, FFMA2 ----
    {
        int o0 = 4 * w;
        bool br1 = (w < 8);
        int oc0 = br1 ? o0 : o0 - 32;
        const float* pwp = br1 ? pw1 : pw2;
        const float* rwp = br1 ? r1w : r2w;
        const float* rbp = br1 ? r1b : r2b;
        const ull* dsrc = (const ull*)(sm + (br1 ? SM_D1 : SM_D2));
        const ull* f2 = (const ull*)(sm + SM_F2);

        ull pr[4][5], shrb[4];
#pragma unroll
        for (int u = 0; u < 4; u++) {
            int o = o0 + u, oc = oc0 + u;
            float sc = g_scale[o];
#pragma unroll
            for (int c = 0; c < 5; c++)
                pr[u][c] = pack2(sc * __ldg(&pwp[oc * 5 + c]), __ldg(&rwp[oc * 5 + c]));
            shrb[u] = pack2(g_shift[o], __ldg(&rbp[oc]));
        }

        ull acc[4][5];
#pragma unroll
        for (int u = 0; u < 4; u++)
#pragma unroll
            for (int p = 0; p < 5; p++) acc[u][p] = 0ULL;

#pragma unroll 2
        for (int it = 0; it < 32; it++) {
            int l = lid + it * 32;
            ull ds[5];
#pragma unroll
            for (int c = 0; c < 5; c++) ds[c] = dsrc[c * 1024 + l];
            ull t[4];
#pragma unroll
            for (int u = 0; u < 4; u++) t[u] = shrb[u];
#pragma unroll
            for (int c = 0; c < 5; c++)
#pragma unroll
                for (int u = 0; u < 4; u++) t[u] = fma2(pr[u][c], ds[c], t[u]);
            ull xp[4];
#pragma unroll
            for (int u = 0; u < 4; u++) {
                float y, z;
                unpack2(t[u], y, z);
                float xv = fmaxf(y, 0.f) * z;
                xp[u] = pack2(xv, xv);
            }
#pragma unroll
            for (int p = 0; p < 5; p++) {
                ull f = f2[p * 1024 + l];
#pragma unroll
                for (int u = 0; u < 4; u++) acc[u][p] = fma2(xp[u], f, acc[u][p]);
            }
        }

        // reduce 40 scalars across the warp
        float a[40];
#pragma unroll
        for (int u = 0; u < 4; u++)
#pragma unroll
            for (int p = 0; p < 5; p++)
                unpack2(acc[u][p], a[u * 10 + 2 * p], a[u * 10 + 2 * p + 1]);
#pragma unroll
        for (int j = 0; j < 40; j++) {
#pragma unroll
            for (int off = 16; off > 0; off >>= 1)
                a[j] += __shfl_xor_sync(0xffffffffu, a[j], off);
        }
        if (lid == 0) {
#pragma unroll
            for (int j = 0; j < 20; j++) sm[SM_S + o0 * 10 + j] = a[j];
        } else if (lid == 1) {
#pragma unroll
            for (int j = 20; j < 40; j++) sm[SM_S + o0 * 10 + j] = a[j];
        }
    }
    __syncthreads();

    // ---- stage 4: PQ[a][n] = sum_c ll1w[a,c]*S[c,n] + ll1b[a]*T[n] ----
    if (tid < 130) {
        int a = tid / 10, n = tid - a * 10;
        float p = __ldg(&ll1b[a]) * g_T[n];
#pragma unroll 8
        for (int c = 0; c < 64; c++) p = fmaf(sm[SM_L + a * 64 + c], sm[SM_S + c * 10 + n], p);
        sm[SM_PQ + tid] = p;
    }
    __syncthreads();

    // ---- stage 5: out[i,j,n] = PQ[min,n] + PQ[max,5+n] + flb[n] ----
    float* outp = out + b * (NA * NA * NBND);
    for (int t = tid; t < NA * NA * NBND; t += 512) {
        int i = t / (NA * NBND);
        int r = t - i * (NA * NBND);
        int j = r / NBND;
        int n = r - j * NBND;
        int mn = min(i, j), mx = max(i, j);
        outp[t] = sm[SM_PQ + mn * 10 + n] + sm[SM_PQ + mx * 10 + 5 + n] + __ldg(&flb[n]);
    }
}

// ---------------------------------------------------------------------------
extern "C" void kernel_launch(void* const* d_in, const int* in_sizes, int n_in,
                              void* d_out, int out_size) {
    const float* src  = (const float*)d_in[0];
    const float* dw1  = (const float*)d_in[3];
    const float* pw1  = (const float*)d_in[4];
    const float* g1   = (const float*)d_in[5];
    const float* be1  = (const float*)d_in[6];
    const float* r1w  = (const float*)d_in[7];
    const float* r1b  = (const float*)d_in[8];
    const float* dw2  = (const float*)d_in[9];
    const float* pw2  = (const float*)d_in[10];
    const float* g2   = (const float*)d_in[11];
    const float* be2  = (const float*)d_in[12];
    const float* r2w  = (const float*)d_in[13];
    const float* r2b  = (const float*)d_in[14];
    const float* ll1w = (const float*)d_in[15];
    const float* ll1b = (const float*)d_in[16];
    const float* flw  = (const float*)d_in[17];
    const float* flb  = (const float*)d_in[18];
    float* out = (float*)d_out;

    cudaFuncSetAttribute(k_main, cudaFuncAttributeMaxDynamicSharedMemorySize, SMEM_BYTES);

    k_stats<<<BATCH, 256>>>(src, dw1, dw2);
    k_finalize<<<1, 256>>>(pw1, g1, be1, pw2, g2, be2, flw);
    k_main<<<BATCH, 512, SMEM_BYTES>>>(src, dw1, dw2, pw1, pw2, r1w, r1b, r2w, r2b,
                                       ll1w, ll1b, flw, flb, out);
}

// round 4
// speedup vs baseline: 1.2568x; 1.1290x over previous
#include <cuda_runtime.h>
#include <math.h>

#define BATCH 512
#define LEN   1024
#define NA    13
#define NBND  5

typedef unsigned long long ull;

__device__ float g_partial[BATCH * 40];
__device__ float g_stats[40];

// ---- f32x2 helpers ----
__device__ __forceinline__ ull pack2(float lo, float hi) {
    ull r; asm("mov.b64 %0, {%1, %2};" : "=l"(r) : "f"(lo), "f"(hi)); return r;
}
__device__ __forceinline__ void unpack2(ull v, float& lo, float& hi) {
    asm("mov.b64 {%0, %1}, %2;" : "=f"(lo), "=f"(hi) : "l"(v));
}
__device__ __forceinline__ ull fma2(ull a, ull b, ull c) {
    ull d; asm("fma.rn.f32x2 %0, %1, %2, %3;" : "=l"(d) : "l"(a), "l"(b), "l"(c)); return d;
}

// ---------------------------------------------------------------------------
// K1: per-batch partials D1[5],G1[15],D2[5],G2[15]
// ---------------------------------------------------------------------------
__global__ __launch_bounds__(256) void k_stats(const float* __restrict__ src,
                                               const float* __restrict__ dw1,
                                               const float* __restrict__ dw2) {
    __shared__ float s_red[8 * 40];
    int b = blockIdx.x, tid = threadIdx.x;
    int l0 = tid * 4;
    const float* sb = src + b * 5 * 1024;

    float w1[5][5], w2[5][3];
#pragma unroll
    for (int c = 0; c < 5; c++) {
#pragma unroll
        for (int k = 0; k < 5; k++) w1[c][k] = __ldg(&dw1[c * 5 + k]);
#pragma unroll
        for (int k = 0; k < 3; k++) w2[c][k] = __ldg(&dw2[c * 3 + k]);
    }

    float x[5][8];
#pragma unroll
    for (int c = 0; c < 5; c++) {
        const float* p = sb + c * 1024 + l0;
        float4 m = *(const float4*)p;
        x[c][2] = m.x; x[c][3] = m.y; x[c][4] = m.z; x[c][5] = m.w;
        if (l0 >= 2) { float2 e = *(const float2*)(p - 2); x[c][0] = e.x; x[c][1] = e.y; }
        else         { x[c][0] = 0.f; x[c][1] = 0.f; }
        if (l0 + 5 < 1024) { float2 e = *(const float2*)(p + 4); x[c][6] = e.x; x[c][7] = e.y; }
        else               { x[c][6] = 0.f; x[c][7] = 0.f; }
    }

    float v[40];
#pragma unroll
    for (int j = 0; j < 40; j++) v[j] = 0.f;

#pragma unroll
    for (int j = 0; j < 4; j++) {
        float d1[5], d2[5];
#pragma unroll
        for (int c = 0; c < 5; c++) {
            float a1 = 0.f;
#pragma unroll
            for (int k = 0; k < 5; k++) a1 = fmaf(w1[c][k], x[c][j + k], a1);
            float a2 = 0.f;
#pragma unroll
            for (int k = 0; k < 3; k++) a2 = fmaf(w2[c][k], x[c][j + k + 1], a2);
            d1[c] = a1; d2[c] = a2;
            v[c] += a1; v[20 + c] += a2;
        }
        int gi = 0;
#pragma unroll
        for (int c = 0; c < 5; c++)
#pragma unroll
            for (int c2 = c; c2 < 5; c2++, gi++) {
                v[5 + gi]  = fmaf(d1[c], d1[c2], v[5 + gi]);
                v[25 + gi] = fmaf(d2[c], d2[c2], v[25 + gi]);
            }
    }

#pragma unroll
    for (int j = 0; j < 40; j++) {
#pragma unroll
        for (int off = 16; off > 0; off >>= 1)
            v[j] += __shfl_xor_sync(0xffffffffu, v[j], off);
    }
    int w = tid >> 5, lid = tid & 31;
    if (lid == 0) {
#pragma unroll
        for (int j = 0; j < 40; j++) s_red[w * 40 + j] = v[j];
    }
    __syncthreads();
    if (tid < 40) {
        float s = 0.f;
#pragma unroll
        for (int k = 0; k < 8; k++) s += s_red[k * 40 + tid];
        g_partial[b * 40 + tid] = s;
    }
}

// ---------------------------------------------------------------------------
// K2: parallel reduce of g_partial -> g_stats[40].  grid=40, block=128.
// ---------------------------------------------------------------------------
__global__ __launch_bounds__(128) void k_reduce() {
    __shared__ float s_w[4];
    int j = blockIdx.x, tid = threadIdx.x;
    float s = 0.f;
#pragma unroll
    for (int k = 0; k < 4; k++) s += g_partial[(tid + k * 128) * 40 + j];
#pragma unroll
    for (int off = 16; off > 0; off >>= 1) s += __shfl_xor_sync(0xffffffffu, s, off);
    if ((tid & 31) == 0) s_w[tid >> 5] = s;
    __syncthreads();
    if (tid == 0) g_stats[j] = s_w[0] + s_w[1] + s_w[2] + s_w[3];
}

// ---------------------------------------------------------------------------
// K3: fused main kernel (BN finalize + T computed per-CTA, no extra kernel).
// ---------------------------------------------------------------------------
#define SM_SRC 0                         // 5*1032 floats
#define SM_D1  (5 * 1032)                // 5*1024 float2 (dc1, src)
#define SM_D2  (SM_D1 + 10240)           // 5*1024 float2 (dc2, src)
#define SM_F2  (SM_D2 + 10240)           // 5*1024 float2 (F[2p], F[2p+1])
#define SM_L   (SM_F2 + 10240)           // 13*64  ll1w
#define SM_S   (SM_L + 832)              // 64*10
#define SM_PQ  (SM_S + 640)              // 13*10
#define SM_ST  (SM_PQ + 130)             // 40 raw stats
#define SM_SC  (SM_ST + 40)              // 64 bn scale
#define SM_SH  (SM_SC + 64)              // 64 bn shift
#define SM_T   (SM_SH + 64)              // 10 T sums
#define SMEM_FLOATS (SM_T + 10)
#define SMEM_BYTES  (SMEM_FLOATS * 4)

__global__ __launch_bounds__(512, 1) void k_main(
    const float* __restrict__ src,
    const float* __restrict__ dw1, const float* __restrict__ dw2,
    const float* __restrict__ pw1, const float* __restrict__ pw2,
    const float* __restrict__ g1, const float* __restrict__ be1,
    const float* __restrict__ g2, const float* __restrict__ be2,
    const float* __restrict__ r1w, const float* __restrict__ r1b,
    const float* __restrict__ r2w, const float* __restrict__ r2b,
    const float* __restrict__ ll1w, const float* __restrict__ ll1b,
    const float* __restrict__ flw, const float* __restrict__ flb,
    float* __restrict__ out) {
    extern __shared__ float sm[];
    int b = blockIdx.x, tid = threadIdx.x;
    int w = tid >> 5, lid = tid & 31;

    // ---- stage 1: src (halo), F2 pairs, ll1w, raw stats ----
    for (int idx = tid; idx < 5 * 1032; idx += 512) {
        int c = idx / 1032, p = idx - c * 1032;
        float v = 0.f;
        if (p >= 2 && p < 1026) v = src[(b * 5 + c) * 1024 + (p - 2)];
        sm[SM_SRC + idx] = v;
    }
    {
        ull* f2 = (ull*)(sm + SM_F2);
        for (int idx = tid; idx < 5 * 1024; idx += 512) {
            int p = idx >> 10, l = idx & 1023;
            int n0 = 2 * p, n1 = 2 * p + 1;
            float v0 = __ldg(&flw[(n0 % 5) * 2048 + (n0 / 5) * 1024 + l]);
            float v1 = __ldg(&flw[(n1 % 5) * 2048 + (n1 / 5) * 1024 + l]);
            f2[idx] = pack2(v0, v1);
        }
    }
    for (int idx = tid; idx < NA * 64; idx += 512) sm[SM_L + idx] = __ldg(&ll1w[idx]);
    if (tid < 40) sm[SM_ST + tid] = g_stats[tid];
    __syncthreads();

    // ---- stage 2: depthwise convs (interleave with src); bn finalize; T ----
    {
        ull* d1 = (ull*)(sm + SM_D1);
        ull* d2 = (ull*)(sm + SM_D2);
        float wa[5][5], wb[5][3];
#pragma unroll
        for (int c = 0; c < 5; c++) {
#pragma unroll
            for (int k = 0; k < 5; k++) wa[c][k] = __ldg(&dw1[c * 5 + k]);
#pragma unroll
            for (int k = 0; k < 3; k++) wb[c][k] = __ldg(&dw2[c * 3 + k]);
        }
#pragma unroll
        for (int i = 0; i < 10; i++) {
            int idx = tid + i * 512;
            int c = idx >> 10, l = idx & 1023;
            const float* sp = &sm[SM_SRC + c * 1032 + l];
            float a1 = 0.f;
#pragma unroll
            for (int k = 0; k < 5; k++) a1 = fmaf(wa[c][k], sp[k], a1);
            float a2 = 0.f;
#pragma unroll
            for (int k = 0; k < 3; k++) a2 = fmaf(wb[c][k], sp[k + 1], a2);
            float sv = sp[2];
            d1[idx] = pack2(a1, sv);
            d2[idx] = pack2(a2, sv);
        }

        // bn finalize: threads 0..63 -> s_SC/s_SH
        if (tid < 64) {
            int o = tid;
            bool br1 = (o < 32);
            int oc = br1 ? o : o - 32;
            const float* pw = br1 ? pw1 : pw2;
            int db = br1 ? 0 : 20;
            float pc[5];
            float m = 0.f;
#pragma unroll
            for (int c = 0; c < 5; c++) {
                pc[c] = __ldg(&pw[oc * 5 + c]);
                m = fmaf(pc[c], sm[SM_ST + db + c], m);
            }
            const float invN = 1.f / (float)(BATCH * LEN);
            m *= invN;
            float e2 = 0.f;
            int gi = 0;
#pragma unroll
            for (int c = 0; c < 5; c++)
#pragma unroll
                for (int c2 = c; c2 < 5; c2++, gi++) {
                    float mult = (c == c2) ? 1.f : 2.f;
                    e2 = fmaf(mult * pc[c] * pc[c2], sm[SM_ST + db + 5 + gi], e2);
                }
            e2 *= invN;
            float var = e2 - m * m;
            float gg = br1 ? __ldg(&g1[oc]) : __ldg(&g2[oc]);
            float bb = br1 ? __ldg(&be1[oc]) : __ldg(&be2[oc]);
            float sc = gg * rsqrtf(var + 1e-5f);
            sm[SM_SC + o] = sc;
            sm[SM_SH + o] = bb - m * sc;
        }

        // T sums from F2 pairs: warps 10..14 handle pair p = w-10
        if (w >= 10 && w < 15) {
            int p = w - 10;
            const ull* f2 = (const ull*)(sm + SM_F2);
            float t0 = 0.f, t1 = 0.f;
#pragma unroll
            for (int k = 0; k < 32; k++) {
                float a, bb2;
                unpack2(f2[p * 1024 + lid + k * 32], a, bb2);
                t0 += a; t1 += bb2;
            }
#pragma unroll
            for (int off = 16; off > 0; off >>= 1) {
                t0 += __shfl_xor_sync(0xffffffffu, t0, off);
                t1 += __shfl_xor_sync(0xffffffffu, t1, off);
            }
            if (lid == 0) { sm[SM_T + 2 * p] = t0; sm[SM_T + 2 * p + 1] = t1; }
        }
    }
    __syncthreads();

    // ---- stage 3: each warp: 4 channels, full L, FFMA2, unroll 1 ----
    {
        int o0 = 4 * w;
        bool br1 = (w < 8);
        int oc0 = br1 ? o0 : o0 - 32;
        const float* pwp = br1 ? pw1 : pw2;
        const float* rwp = br1 ? r1w : r2w;
        const float* rbp = br1 ? r1b : r2b;
        const ull* dsrc = (const ull*)(sm + (br1 ? SM_D1 : SM_D2));
        const ull* f2 = (const ull*)(sm + SM_F2);

        ull pr[4][5], shrb[4];
#pragma unroll
        for (int u = 0; u < 4; u++) {
            int o = o0 + u, oc = oc0 + u;
            float sc = sm[SM_SC + o];
#pragma unroll
            for (int c = 0; c < 5; c++)
                pr[u][c] = pack2(sc * __ldg(&pwp[oc * 5 + c]), __ldg(&rwp[oc * 5 + c]));
            shrb[u] = pack2(sm[SM_SH + o], __ldg(&rbp[oc]));
        }

        ull acc[4][5];
#pragma unroll
        for (int u = 0; u < 4; u++)
#pragma unroll
            for (int p = 0; p < 5; p++) acc[u][p] = 0ULL;

#pragma unroll 1
        for (int it = 0; it < 32; it++) {
            int l = lid + it * 32;
            ull ds[5];
#pragma unroll
            for (int c = 0; c < 5; c++) ds[c] = dsrc[c * 1024 + l];
            ull t[4];
#pragma unroll
            for (int u = 0; u < 4; u++) t[u] = fma2(pr[u][0], ds[0], shrb[u]);
#pragma unroll
            for (int c = 1; c < 5; c++)
#pragma unroll
                for (int u = 0; u < 4; u++) t[u] = fma2(pr[u][c], ds[c], t[u]);
#pragma unroll
            for (int u = 0; u < 4; u++) {
                float y, z;
                unpack2(t[u], y, z);
                float xv = fmaxf(y, 0.f) * z;
                t[u] = pack2(xv, xv);
            }
#pragma unroll
            for (int p = 0; p < 5; p++) {
                ull f = f2[p * 1024 + l];
#pragma unroll
                for (int u = 0; u < 4; u++) acc[u][p] = fma2(t[u], f, acc[u][p]);
            }
        }

        float a[40];
#pragma unroll
        for (int u = 0; u < 4; u++)
#pragma unroll
            for (int p = 0; p < 5; p++)
                unpack2(acc[u][p], a[u * 10 + 2 * p], a[u * 10 + 2 * p + 1]);
#pragma unroll
        for (int j = 0; j < 40; j++) {
#pragma unroll
            for (int off = 16; off > 0; off >>= 1)
                a[j] += __shfl_xor_sync(0xffffffffu, a[j], off);
        }
        if (lid == 0) {
#pragma unroll
            for (int j = 0; j < 20; j++) sm[SM_S + o0 * 10 + j] = a[j];
        } else if (lid == 1) {
#pragma unroll
            for (int j = 20; j < 40; j++) sm[SM_S + o0 * 10 + j] = a[j];
        }
    }
    __syncthreads();

    // ---- stage 4: PQ[a][n] = sum_c ll1w[a,c]*S[c,n] + ll1b[a]*T[n] ----
    if (tid < 130) {
        int a = tid / 10, n = tid - a * 10;
        float p = __ldg(&ll1b[a]) * sm[SM_T + n];
#pragma unroll 8
        for (int c = 0; c < 64; c++) p = fmaf(sm[SM_L + a * 64 + c], sm[SM_S + c * 10 + n], p);
        sm[SM_PQ + tid] = p;
    }
    __syncthreads();

    // ---- stage 5: out ----
    float* outp = out + b * (NA * NA * NBND);
    for (int t = tid; t < NA * NA * NBND; t += 512) {
        int i = t / (NA * NBND);
        int r = t - i * (NA * NBND);
        int j = r / NBND;
        int n = r - j * NBND;
        int mn = min(i, j), mx = max(i, j);
        outp[t] = sm[SM_PQ + mn * 10 + n] + sm[SM_PQ + mx * 10 + 5 + n] + __ldg(&flb[n]);
    }
}

// ---------------------------------------------------------------------------
extern "C" void kernel_launch(void* const* d_in, const int* in_sizes, int n_in,
                              void* d_out, int out_size) {
    const float* src  = (const float*)d_in[0];
    const float* dw1  = (const float*)d_in[3];
    const float* pw1  = (const float*)d_in[4];
    const float* g1   = (const float*)d_in[5];
    const float* be1  = (const float*)d_in[6];
    const float* r1w  = (const float*)d_in[7];
    const float* r1b  = (const float*)d_in[8];
    const float* dw2  = (const float*)d_in[9];
    const float* pw2  = (const float*)d_in[10];
    const float* g2   = (const float*)d_in[11];
    const float* be2  = (const float*)d_in[12];
    const float* r2w  = (const float*)d_in[13];
    const float* r2b  = (const float*)d_in[14];
    const float* ll1w = (const float*)d_in[15];
    const float* ll1b = (const float*)d_in[16];
    const float* flw  = (const float*)d_in[17];
    const float* flb  = (const float*)d_in[18];
    float* out = (float*)d_out;

    cudaFuncSetAttribute(k_main, cudaFuncAttributeMaxDynamicSharedMemorySize, SMEM_BYTES);

    k_stats<<<BATCH, 256>>>(src, dw1, dw2);
    k_reduce<<<40, 128>>>();
    k_main<<<BATCH, 512, SMEM_BYTES>>>(src, dw1, dw2, pw1, pw2, g1, be1, g2, be2,
                                       r1w, r1b, r2w, r2b, ll1w, ll1b, flw, flb, out);
}